// round 2
// baseline (speedup 1.0000x reference)
#include <cuda_runtime.h>
#include <math.h>

#define DD 256
#define AA 64
#define NROWS 4096   // B*N = 16*256

// ---------------- scratch (device globals; no allocation allowed) ----------
__device__ float g_W2[DD * DD];      // scale * Wq^T @ Wk
__device__ float g_b2[DD];           // scale * bq @ Wk
__device__ float g_u[DD];            // scale * Wq^T @ bk
__device__ float g_c;                // scale * bq . bk
__device__ float g_Qk[NROWS * DD];   // cc @ g_W2 + g_b2
__device__ float g_wsum[NROWS * DD]; // sum_a p[a] * anchor[a,:]
__device__ float g_S[NROWS];         // sum_a p[a]

// ---------------- shared 4x4 micro-kernel ----------------------------------
__device__ __forceinline__ void mma_tile(const float (*As)[68], const float (*Bs)[68],
                                         int ty, int tx, float acc[4][4]) {
#pragma unroll
    for (int kk = 0; kk < 16; ++kk) {
        float4 av = *reinterpret_cast<const float4*>(&As[kk][ty * 4]);
        float4 bv = *reinterpret_cast<const float4*>(&Bs[kk][tx * 4]);
        float ar[4] = {av.x, av.y, av.z, av.w};
        float br[4] = {bv.x, bv.y, bv.z, bv.w};
#pragma unroll
        for (int i = 0; i < 4; ++i)
#pragma unroll
            for (int j = 0; j < 4; ++j)
                acc[i][j] = fmaf(ar[i], br[j], acc[i][j]);
    }
}

// ---------------- kernel A: g_W2 = scale * Wq^T @ Wk ------------------------
__global__ __launch_bounds__(256) void prep_w2(const float* __restrict__ Wq,
                                               const float* __restrict__ Wk) {
    __shared__ float As[16][68];
    __shared__ float Bs[16][68];
    const float scale = 0.0625f;  // 1/sqrt(256)
    int tx = threadIdx.x % 16, ty = threadIdx.x / 16;
    int d0 = blockIdx.x * 64, e0 = blockIdx.y * 64;
    float acc[4][4] = {};
    for (int k0 = 0; k0 < DD; k0 += 16) {
        // Wq^T tile: As[k][m] = Wq[(k0+k)*D + d0+m]  (no transpose needed)
        float4 a = *reinterpret_cast<const float4*>(Wq + (k0 + ty) * DD + d0 + tx * 4);
        float4 b = *reinterpret_cast<const float4*>(Wk + (k0 + ty) * DD + e0 + tx * 4);
        *reinterpret_cast<float4*>(&As[ty][tx * 4]) = a;
        *reinterpret_cast<float4*>(&Bs[ty][tx * 4]) = b;
        __syncthreads();
        mma_tile(As, Bs, ty, tx, acc);
        __syncthreads();
    }
#pragma unroll
    for (int i = 0; i < 4; ++i)
#pragma unroll
        for (int j = 0; j < 4; ++j)
            g_W2[(d0 + ty * 4 + i) * DD + e0 + tx * 4 + j] = scale * acc[i][j];
}

// ---------------- kernel A2: bias vectors ----------------------------------
__global__ __launch_bounds__(256) void prep_vec(const float* __restrict__ Wq,
                                                const float* __restrict__ bq,
                                                const float* __restrict__ Wk,
                                                const float* __restrict__ bk) {
    const float scale = 0.0625f;
    int t = threadIdx.x;
    if (blockIdx.x == 0) {
        float s = 0.f;
        for (int k = 0; k < DD; ++k) s = fmaf(Wq[k * DD + t], bk[k], s);
        g_u[t] = scale * s;
        if (t == 0) {
            float c = 0.f;
            for (int k = 0; k < DD; ++k) c = fmaf(bq[k], bk[k], c);
            g_c = scale * c;
        }
    } else {
        float s = 0.f;
        for (int k = 0; k < DD; ++k) s = fmaf(bq[k], Wk[k * DD + t], s);
        g_b2[t] = scale * s;
    }
}

// ---------------- kernel B: g_Qk = cc @ g_W2 + g_b2 -------------------------
__global__ __launch_bounds__(256) void gemm_qk(const float* __restrict__ Acc) {
    __shared__ float As[16][68];
    __shared__ float Bs[16][68];
    int tx = threadIdx.x % 16, ty = threadIdx.x / 16;
    int m0 = blockIdx.x * 64, n0 = blockIdx.y * 64;
    int lm = threadIdx.x / 4, lkg = threadIdx.x % 4;
    float acc[4][4] = {};
    for (int k0 = 0; k0 < DD; k0 += 16) {
        float4 a = *reinterpret_cast<const float4*>(Acc + (m0 + lm) * DD + k0 + lkg * 4);
        As[lkg * 4 + 0][lm] = a.x;
        As[lkg * 4 + 1][lm] = a.y;
        As[lkg * 4 + 2][lm] = a.z;
        As[lkg * 4 + 3][lm] = a.w;
        float4 b = *reinterpret_cast<const float4*>(g_W2 + (k0 + ty) * DD + n0 + tx * 4);
        *reinterpret_cast<float4*>(&Bs[ty][tx * 4]) = b;
        __syncthreads();
        mma_tile(As, Bs, ty, tx, acc);
        __syncthreads();
    }
#pragma unroll
    for (int i = 0; i < 4; ++i)
#pragma unroll
        for (int j = 0; j < 4; ++j)
            g_Qk[(m0 + ty * 4 + i) * DD + n0 + tx * 4 + j] =
                acc[i][j] + g_b2[n0 + tx * 4 + j];
}

// ---------------- kernel C: fused scores + softmax + weighted sum ----------
__global__ __launch_bounds__(256) void attn_fused(const float* __restrict__ anchor,
                                                  const float* __restrict__ sims,
                                                  const float* __restrict__ cc) {
    extern __shared__ float sm[];
    float* sA = sm;              // [64][256] anchor tile
    float* sQk = sm + AA * DD;   // [256]
    __shared__ float s_adj[AA];
    __shared__ float s_p[AA];
    __shared__ float s_red[8];

    const int t = threadIdx.x;
    const int row = blockIdx.x;
    const int w = t >> 5, lane = t & 31;

    // Qk row
    sQk[t] = g_Qk[row * DD + t];

    // qb = cc_row . g_u + g_c   (block reduce)
    float pv = cc[row * DD + t] * g_u[t];
#pragma unroll
    for (int o = 16; o; o >>= 1) pv += __shfl_down_sync(0xffffffffu, pv, o);
    if (lane == 0) s_red[w] = pv;

    // anchor tile -> smem (64 KB, float4 coalesced)
    const float4* a4 = reinterpret_cast<const float4*>(anchor + (size_t)row * AA * DD);
    float4* sA4 = reinterpret_cast<float4*>(sA);
#pragma unroll
    for (int i = 0; i < 16; ++i) sA4[t + i * 256] = a4[t + i * 256];
    __syncthreads();

    float qb;
    {
        float s = s_red[0];
#pragma unroll
        for (int i = 1; i < 8; ++i) s += s_red[i];
        qb = s + g_c;
    }

    // scores: warp w handles rows a = w + 8*r
#pragma unroll
    for (int r = 0; r < 8; ++r) {
        int a = w + r * 8;
        const float* ar = sA + a * DD;
        float s = 0.f;
#pragma unroll
        for (int j = 0; j < 8; ++j) s = fmaf(sQk[lane + 32 * j], ar[lane + 32 * j], s);
#pragma unroll
        for (int o = 16; o; o >>= 1) s += __shfl_down_sync(0xffffffffu, s, o);
        if (lane == 0) s_adj[a] = s + qb + sims[row * AA + a];
    }
    __syncthreads();

    // conditional softmax (warp 0 owns all 64 logits)
    if (w == 0) {
        float v0 = s_adj[lane], v1 = s_adj[lane + 32];
        float sum = v0 + v1;
#pragma unroll
        for (int o = 16; o; o >>= 1) sum += __shfl_xor_sync(0xffffffffu, sum, o);
        if (sum != 0.0f) {
            float m = fmaxf(v0, v1);
#pragma unroll
            for (int o = 16; o; o >>= 1) m = fmaxf(m, __shfl_xor_sync(0xffffffffu, m, o));
            float e0 = expf(v0 - m), e1 = expf(v1 - m);
            float es = e0 + e1;
#pragma unroll
            for (int o = 16; o; o >>= 1) es += __shfl_xor_sync(0xffffffffu, es, o);
            float p0 = e0 / es, p1 = e1 / es;
            s_p[lane] = p0;
            s_p[lane + 32] = p1;
            float ps = p0 + p1;
#pragma unroll
            for (int o = 16; o; o >>= 1) ps += __shfl_xor_sync(0xffffffffu, ps, o);
            if (lane == 0) g_S[row] = ps;
        } else {
            s_p[lane] = v0;
            s_p[lane + 32] = v1;
            if (lane == 0) g_S[row] = sum;  // == 0
        }
    }
    __syncthreads();

    // weighted sum over the smem tile: wsum[e] = sum_a p[a]*anchor[a][e]
    float acc0 = 0.f, acc1 = 0.f;
#pragma unroll
    for (int a = 0; a < AA; a += 2) {
        acc0 = fmaf(s_p[a + 0], sA[(a + 0) * DD + t], acc0);
        acc1 = fmaf(s_p[a + 1], sA[(a + 1) * DD + t], acc1);
    }
    g_wsum[row * DD + t] = acc0 + acc1;
}

// ---------------- kernel D: out = g_wsum @ Wv^T + bv * S --------------------
__global__ __launch_bounds__(256) void gemm_out(const float* __restrict__ Wv,
                                                const float* __restrict__ bv,
                                                float* __restrict__ out) {
    __shared__ float As[16][68];
    __shared__ float Bs[16][68];
    int tx = threadIdx.x % 16, ty = threadIdx.x / 16;
    int m0 = blockIdx.x * 64, n0 = blockIdx.y * 64;
    int lm = threadIdx.x / 4, lkg = threadIdx.x % 4;
    float acc[4][4] = {};
    for (int k0 = 0; k0 < DD; k0 += 16) {
        float4 a = *reinterpret_cast<const float4*>(g_wsum + (m0 + lm) * DD + k0 + lkg * 4);
        As[lkg * 4 + 0][lm] = a.x;
        As[lkg * 4 + 1][lm] = a.y;
        As[lkg * 4 + 2][lm] = a.z;
        As[lkg * 4 + 3][lm] = a.w;
        // Bs[k][n] = Wv[(n0+n)*D + k0+k]   (transposed load)
        float4 b = *reinterpret_cast<const float4*>(Wv + (n0 + lm) * DD + k0 + lkg * 4);
        Bs[lkg * 4 + 0][lm] = b.x;
        Bs[lkg * 4 + 1][lm] = b.y;
        Bs[lkg * 4 + 2][lm] = b.z;
        Bs[lkg * 4 + 3][lm] = b.w;
        __syncthreads();
        mma_tile(As, Bs, ty, tx, acc);
        __syncthreads();
    }
#pragma unroll
    for (int i = 0; i < 4; ++i) {
        int m = m0 + ty * 4 + i;
        float Sv = g_S[m];
#pragma unroll
        for (int j = 0; j < 4; ++j)
            out[m * DD + n0 + tx * 4 + j] = acc[i][j] + bv[n0 + tx * 4 + j] * Sv;
    }
}

// ---------------- launch ----------------------------------------------------
extern "C" void kernel_launch(void* const* d_in, const int* in_sizes, int n_in,
                              void* d_out, int out_size) {
    const float* cc     = (const float*)d_in[0];
    const float* anchor = (const float*)d_in[1];
    const float* sims   = (const float*)d_in[2];
    const float* Wq     = (const float*)d_in[3];
    const float* bq     = (const float*)d_in[4];
    const float* Wk     = (const float*)d_in[5];
    const float* bk     = (const float*)d_in[6];
    const float* Wv     = (const float*)d_in[7];
    const float* bv     = (const float*)d_in[8];
    float* out = (float*)d_out;

    const int smem_attn = (AA * DD + DD) * (int)sizeof(float);  // 66560 B
    cudaFuncSetAttribute(attn_fused, cudaFuncAttributeMaxDynamicSharedMemorySize,
                         smem_attn);

    prep_w2<<<dim3(4, 4), 256>>>(Wq, Wk);
    prep_vec<<<2, 256>>>(Wq, bq, Wk, bk);
    gemm_qk<<<dim3(64, 4), 256>>>(cc);
    attn_fused<<<NROWS, 256, smem_attn>>>(anchor, sims, cc);
    gemm_out<<<dim3(64, 4), 256>>>(Wv, bv, out);
}

// round 3
// speedup vs baseline: 1.0090x; 1.0090x over previous
#include <cuda_runtime.h>
#include <math.h>

#define DD 256
#define AA 64
#define NROWS 4096   // B*N = 16*256

// ---------------- scratch (device globals; no allocation allowed) ----------
__device__ float g_W2[DD * DD];      // scale * Wq^T @ Wk
__device__ float g_b2[DD];           // scale * bq @ Wk
__device__ float g_u[DD];            // scale * Wq^T @ bk
__device__ float g_c;                // scale * bq . bk
__device__ float g_Qk[NROWS * DD];   // cc @ g_W2 + g_b2
__device__ float g_wsum[NROWS * DD]; // sum_a p[a] * anchor[a,:]
__device__ float g_S[NROWS];         // sum_a p[a]

// ---------------- shared 4x4 micro-kernel ----------------------------------
__device__ __forceinline__ void mma_tile(const float (*As)[68], const float (*Bs)[68],
                                         int ty, int tx, float acc[4][4]) {
#pragma unroll
    for (int kk = 0; kk < 16; ++kk) {
        float4 av = *reinterpret_cast<const float4*>(&As[kk][ty * 4]);
        float4 bv = *reinterpret_cast<const float4*>(&Bs[kk][tx * 4]);
        float ar[4] = {av.x, av.y, av.z, av.w};
        float br[4] = {bv.x, bv.y, bv.z, bv.w};
#pragma unroll
        for (int i = 0; i < 4; ++i)
#pragma unroll
            for (int j = 0; j < 4; ++j)
                acc[i][j] = fmaf(ar[i], br[j], acc[i][j]);
    }
}

// ---------------- kernel A: g_W2 = scale * Wq^T @ Wk ------------------------
__global__ __launch_bounds__(256) void prep_w2(const float* __restrict__ Wq,
                                               const float* __restrict__ Wk) {
    __shared__ float As[16][68];
    __shared__ float Bs[16][68];
    const float scale = 0.0625f;  // 1/sqrt(256)
    int tx = threadIdx.x % 16, ty = threadIdx.x / 16;
    int d0 = blockIdx.x * 64, e0 = blockIdx.y * 64;
    float acc[4][4] = {};
    for (int k0 = 0; k0 < DD; k0 += 16) {
        // Wq^T tile: As[k][m] = Wq[(k0+k)*D + d0+m]  (no transpose needed)
        float4 a = *reinterpret_cast<const float4*>(Wq + (k0 + ty) * DD + d0 + tx * 4);
        float4 b = *reinterpret_cast<const float4*>(Wk + (k0 + ty) * DD + e0 + tx * 4);
        *reinterpret_cast<float4*>(&As[ty][tx * 4]) = a;
        *reinterpret_cast<float4*>(&Bs[ty][tx * 4]) = b;
        __syncthreads();
        mma_tile(As, Bs, ty, tx, acc);
        __syncthreads();
    }
#pragma unroll
    for (int i = 0; i < 4; ++i)
#pragma unroll
        for (int j = 0; j < 4; ++j)
            g_W2[(d0 + ty * 4 + i) * DD + e0 + tx * 4 + j] = scale * acc[i][j];
}

// ---------------- kernel A2: bias vectors ----------------------------------
__global__ __launch_bounds__(256) void prep_vec(const float* __restrict__ Wq,
                                                const float* __restrict__ bq,
                                                const float* __restrict__ Wk,
                                                const float* __restrict__ bk) {
    const float scale = 0.0625f;
    int t = threadIdx.x;
    if (blockIdx.x == 0) {
        float s = 0.f;
        for (int k = 0; k < DD; ++k) s = fmaf(Wq[k * DD + t], bk[k], s);
        g_u[t] = scale * s;
        if (t == 0) {
            float c = 0.f;
            for (int k = 0; k < DD; ++k) c = fmaf(bq[k], bk[k], c);
            g_c = scale * c;
        }
    } else {
        float s = 0.f;
        for (int k = 0; k < DD; ++k) s = fmaf(bq[k], Wk[k * DD + t], s);
        g_b2[t] = scale * s;
    }
}

// ---------------- kernel B: g_Qk = cc @ g_W2 + g_b2 -------------------------
__global__ __launch_bounds__(256) void gemm_qk(const float* __restrict__ Acc) {
    __shared__ float As[16][68];
    __shared__ float Bs[16][68];
    int tx = threadIdx.x % 16, ty = threadIdx.x / 16;
    int m0 = blockIdx.x * 64, n0 = blockIdx.y * 64;
    int lm = threadIdx.x / 4, lkg = threadIdx.x % 4;
    float acc[4][4] = {};
    for (int k0 = 0; k0 < DD; k0 += 16) {
        float4 a = *reinterpret_cast<const float4*>(Acc + (m0 + lm) * DD + k0 + lkg * 4);
        As[lkg * 4 + 0][lm] = a.x;
        As[lkg * 4 + 1][lm] = a.y;
        As[lkg * 4 + 2][lm] = a.z;
        As[lkg * 4 + 3][lm] = a.w;
        float4 b = *reinterpret_cast<const float4*>(g_W2 + (k0 + ty) * DD + n0 + tx * 4);
        *reinterpret_cast<float4*>(&Bs[ty][tx * 4]) = b;
        __syncthreads();
        mma_tile(As, Bs, ty, tx, acc);
        __syncthreads();
    }
#pragma unroll
    for (int i = 0; i < 4; ++i)
#pragma unroll
        for (int j = 0; j < 4; ++j)
            g_Qk[(m0 + ty * 4 + i) * DD + n0 + tx * 4 + j] =
                acc[i][j] + g_b2[n0 + tx * 4 + j];
}

// ---------------- kernel C: fused scores + softmax + weighted sum ----------
__global__ __launch_bounds__(256) void attn_fused(const float* __restrict__ anchor,
                                                  const float* __restrict__ sims,
                                                  const float* __restrict__ cc) {
    extern __shared__ float sm[];
    float* sA = sm;              // [64][256] anchor tile
    float* sQk = sm + AA * DD;   // [256]
    __shared__ float s_adj[AA];
    __shared__ float s_p[AA];
    __shared__ float s_red[8];

    const int t = threadIdx.x;
    const int row = blockIdx.x;
    const int w = t >> 5, lane = t & 31;

    // Qk row
    sQk[t] = g_Qk[row * DD + t];

    // qb = cc_row . g_u + g_c   (block reduce)
    float pv = cc[row * DD + t] * g_u[t];
#pragma unroll
    for (int o = 16; o; o >>= 1) pv += __shfl_down_sync(0xffffffffu, pv, o);
    if (lane == 0) s_red[w] = pv;

    // anchor tile -> smem (64 KB, float4 coalesced)
    const float4* a4 = reinterpret_cast<const float4*>(anchor + (size_t)row * AA * DD);
    float4* sA4 = reinterpret_cast<float4*>(sA);
#pragma unroll
    for (int i = 0; i < 16; ++i) sA4[t + i * 256] = a4[t + i * 256];
    __syncthreads();

    float qb;
    {
        float s = s_red[0];
#pragma unroll
        for (int i = 1; i < 8; ++i) s += s_red[i];
        qb = s + g_c;
    }

    // scores: warp w handles rows a = w + 8*r
#pragma unroll
    for (int r = 0; r < 8; ++r) {
        int a = w + r * 8;
        const float* ar = sA + a * DD;
        float s = 0.f;
#pragma unroll
        for (int j = 0; j < 8; ++j) s = fmaf(sQk[lane + 32 * j], ar[lane + 32 * j], s);
#pragma unroll
        for (int o = 16; o; o >>= 1) s += __shfl_down_sync(0xffffffffu, s, o);
        if (lane == 0) s_adj[a] = s + qb + sims[row * AA + a];
    }
    __syncthreads();

    // conditional softmax (warp 0 owns all 64 logits)
    if (w == 0) {
        float v0 = s_adj[lane], v1 = s_adj[lane + 32];
        float sum = v0 + v1;
#pragma unroll
        for (int o = 16; o; o >>= 1) sum += __shfl_xor_sync(0xffffffffu, sum, o);
        if (sum != 0.0f) {
            float m = fmaxf(v0, v1);
#pragma unroll
            for (int o = 16; o; o >>= 1) m = fmaxf(m, __shfl_xor_sync(0xffffffffu, m, o));
            float e0 = expf(v0 - m), e1 = expf(v1 - m);
            float es = e0 + e1;
#pragma unroll
            for (int o = 16; o; o >>= 1) es += __shfl_xor_sync(0xffffffffu, es, o);
            float p0 = e0 / es, p1 = e1 / es;
            s_p[lane] = p0;
            s_p[lane + 32] = p1;
            float ps = p0 + p1;
#pragma unroll
            for (int o = 16; o; o >>= 1) ps += __shfl_xor_sync(0xffffffffu, ps, o);
            if (lane == 0) g_S[row] = ps;
        } else {
            s_p[lane] = v0;
            s_p[lane + 32] = v1;
            if (lane == 0) g_S[row] = sum;  // == 0
        }
    }
    __syncthreads();

    // weighted sum over the smem tile: wsum[e] = sum_a p[a]*anchor[a][e]
    float acc0 = 0.f, acc1 = 0.f;
#pragma unroll
    for (int a = 0; a < AA; a += 2) {
        acc0 = fmaf(s_p[a + 0], sA[(a + 0) * DD + t], acc0);
        acc1 = fmaf(s_p[a + 1], sA[(a + 1) * DD + t], acc1);
    }
    g_wsum[row * DD + t] = acc0 + acc1;
}

// ---------------- kernel D: out = g_wsum @ Wv^T + bv * S --------------------
__global__ __launch_bounds__(256) void gemm_out(const float* __restrict__ Wv,
                                                const float* __restrict__ bv,
                                                float* __restrict__ out) {
    __shared__ float As[16][68];
    __shared__ float Bs[16][68];
    int tx = threadIdx.x % 16, ty = threadIdx.x / 16;
    int m0 = blockIdx.x * 64, n0 = blockIdx.y * 64;
    int lm = threadIdx.x / 4, lkg = threadIdx.x % 4;
    float acc[4][4] = {};
    for (int k0 = 0; k0 < DD; k0 += 16) {
        float4 a = *reinterpret_cast<const float4*>(g_wsum + (m0 + lm) * DD + k0 + lkg * 4);
        As[lkg * 4 + 0][lm] = a.x;
        As[lkg * 4 + 1][lm] = a.y;
        As[lkg * 4 + 2][lm] = a.z;
        As[lkg * 4 + 3][lm] = a.w;
        // Bs[k][n] = Wv[(n0+n)*D + k0+k]   (transposed load)
        float4 b = *reinterpret_cast<const float4*>(Wv + (n0 + lm) * DD + k0 + lkg * 4);
        Bs[lkg * 4 + 0][lm] = b.x;
        Bs[lkg * 4 + 1][lm] = b.y;
        Bs[lkg * 4 + 2][lm] = b.z;
        Bs[lkg * 4 + 3][lm] = b.w;
        __syncthreads();
        mma_tile(As, Bs, ty, tx, acc);
        __syncthreads();
    }
#pragma unroll
    for (int i = 0; i < 4; ++i) {
        int m = m0 + ty * 4 + i;
        float Sv = g_S[m];
#pragma unroll
        for (int j = 0; j < 4; ++j)
            out[m * DD + n0 + tx * 4 + j] = acc[i][j] + bv[n0 + tx * 4 + j] * Sv;
    }
}

// ---------------- launch ----------------------------------------------------
extern "C" void kernel_launch(void* const* d_in, const int* in_sizes, int n_in,
                              void* d_out, int out_size) {
    const float* cc     = (const float*)d_in[0];
    const float* anchor = (const float*)d_in[1];
    const float* sims   = (const float*)d_in[2];
    const float* Wq     = (const float*)d_in[3];
    const float* bq     = (const float*)d_in[4];
    const float* Wk     = (const float*)d_in[5];
    const float* bk     = (const float*)d_in[6];
    const float* Wv     = (const float*)d_in[7];
    const float* bv     = (const float*)d_in[8];
    float* out = (float*)d_out;

    const int smem_attn = (AA * DD + DD) * (int)sizeof(float);  // 66560 B
    cudaFuncSetAttribute(attn_fused, cudaFuncAttributeMaxDynamicSharedMemorySize,
                         smem_attn);

    prep_w2<<<dim3(4, 4), 256>>>(Wq, Wk);
    prep_vec<<<2, 256>>>(Wq, bq, Wk, bk);
    gemm_qk<<<dim3(64, 4), 256>>>(cc);
    attn_fused<<<NROWS, 256, smem_attn>>>(anchor, sims, cc);
    gemm_out<<<dim3(64, 4), 256>>>(Wv, bv, out);
}

// round 4
// speedup vs baseline: 1.0108x; 1.0018x over previous
#include <cuda_runtime.h>
#include <math.h>

#define DD 256
#define AA 64
#define NROWS 4096   // B*N = 16*256

// ---------------- scratch (device globals; no allocation allowed) ----------
__device__ float g_W2[DD * DD];      // scale * Wq^T @ Wk
__device__ float g_b2[DD];           // scale * bq @ Wk
__device__ float g_u[DD];            // scale * Wq^T @ bk
__device__ float g_c;                // scale * bq . bk
__device__ float g_Qk[NROWS * DD];   // cc @ g_W2 + g_b2
__device__ float g_wsum[NROWS * DD]; // sum_a p[a] * anchor[a,:]
__device__ float g_S[NROWS];         // sum_a p[a]

// ---------------- shared 4x4 micro-kernel ----------------------------------
__device__ __forceinline__ void mma_tile(const float (*As)[68], const float (*Bs)[68],
                                         int ty, int tx, float acc[4][4]) {
#pragma unroll
    for (int kk = 0; kk < 16; ++kk) {
        float4 av = *reinterpret_cast<const float4*>(&As[kk][ty * 4]);
        float4 bv = *reinterpret_cast<const float4*>(&Bs[kk][tx * 4]);
        float ar[4] = {av.x, av.y, av.z, av.w};
        float br[4] = {bv.x, bv.y, bv.z, bv.w};
#pragma unroll
        for (int i = 0; i < 4; ++i)
#pragma unroll
            for (int j = 0; j < 4; ++j)
                acc[i][j] = fmaf(ar[i], br[j], acc[i][j]);
    }
}

// ---------------- kernel A: g_W2 = scale * Wq^T @ Wk ------------------------
__global__ __launch_bounds__(256) void prep_w2(const float* __restrict__ Wq,
                                               const float* __restrict__ Wk) {
    __shared__ float As[16][68];
    __shared__ float Bs[16][68];
    const float scale = 0.0625f;  // 1/sqrt(256)
    int tx = threadIdx.x % 16, ty = threadIdx.x / 16;
    int d0 = blockIdx.x * 64, e0 = blockIdx.y * 64;
    float acc[4][4] = {};
    for (int k0 = 0; k0 < DD; k0 += 16) {
        // Wq^T tile: As[k][m] = Wq[(k0+k)*D + d0+m]  (no transpose needed)
        float4 a = *reinterpret_cast<const float4*>(Wq + (k0 + ty) * DD + d0 + tx * 4);
        float4 b = *reinterpret_cast<const float4*>(Wk + (k0 + ty) * DD + e0 + tx * 4);
        *reinterpret_cast<float4*>(&As[ty][tx * 4]) = a;
        *reinterpret_cast<float4*>(&Bs[ty][tx * 4]) = b;
        __syncthreads();
        mma_tile(As, Bs, ty, tx, acc);
        __syncthreads();
    }
#pragma unroll
    for (int i = 0; i < 4; ++i)
#pragma unroll
        for (int j = 0; j < 4; ++j)
            g_W2[(d0 + ty * 4 + i) * DD + e0 + tx * 4 + j] = scale * acc[i][j];
}

// ---------------- kernel A2: bias vectors ----------------------------------
__global__ __launch_bounds__(256) void prep_vec(const float* __restrict__ Wq,
                                                const float* __restrict__ bq,
                                                const float* __restrict__ Wk,
                                                const float* __restrict__ bk) {
    const float scale = 0.0625f;
    int t = threadIdx.x;
    if (blockIdx.x == 0) {
        float s = 0.f;
        for (int k = 0; k < DD; ++k) s = fmaf(Wq[k * DD + t], bk[k], s);
        g_u[t] = scale * s;
        if (t == 0) {
            float c = 0.f;
            for (int k = 0; k < DD; ++k) c = fmaf(bq[k], bk[k], c);
            g_c = scale * c;
        }
    } else {
        float s = 0.f;
        for (int k = 0; k < DD; ++k) s = fmaf(bq[k], Wk[k * DD + t], s);
        g_b2[t] = scale * s;
    }
}

// ---------------- kernel B: g_Qk = cc @ g_W2 + g_b2 -------------------------
__global__ __launch_bounds__(256) void gemm_qk(const float* __restrict__ Acc) {
    __shared__ float As[16][68];
    __shared__ float Bs[16][68];
    int tx = threadIdx.x % 16, ty = threadIdx.x / 16;
    int m0 = blockIdx.x * 64, n0 = blockIdx.y * 64;
    int lm = threadIdx.x / 4, lkg = threadIdx.x % 4;
    float acc[4][4] = {};
    for (int k0 = 0; k0 < DD; k0 += 16) {
        float4 a = *reinterpret_cast<const float4*>(Acc + (m0 + lm) * DD + k0 + lkg * 4);
        As[lkg * 4 + 0][lm] = a.x;
        As[lkg * 4 + 1][lm] = a.y;
        As[lkg * 4 + 2][lm] = a.z;
        As[lkg * 4 + 3][lm] = a.w;
        float4 b = *reinterpret_cast<const float4*>(g_W2 + (k0 + ty) * DD + n0 + tx * 4);
        *reinterpret_cast<float4*>(&Bs[ty][tx * 4]) = b;
        __syncthreads();
        mma_tile(As, Bs, ty, tx, acc);
        __syncthreads();
    }
#pragma unroll
    for (int i = 0; i < 4; ++i)
#pragma unroll
        for (int j = 0; j < 4; ++j)
            g_Qk[(m0 + ty * 4 + i) * DD + n0 + tx * 4 + j] =
                acc[i][j] + g_b2[n0 + tx * 4 + j];
}

// ---------------- kernel C: fused scores + softmax + weighted sum ----------
__global__ __launch_bounds__(256) void attn_fused(const float* __restrict__ anchor,
                                                  const float* __restrict__ sims,
                                                  const float* __restrict__ cc) {
    extern __shared__ float sm[];
    float* sA = sm;              // [64][256] anchor tile
    float* sQk = sm + AA * DD;   // [256]
    __shared__ float s_adj[AA];
    __shared__ float s_p[AA];
    __shared__ float s_red[8];

    const int t = threadIdx.x;
    const int row = blockIdx.x;
    const int w = t >> 5, lane = t & 31;

    // Qk row
    sQk[t] = g_Qk[row * DD + t];

    // qb = cc_row . g_u + g_c   (block reduce)
    float pv = cc[row * DD + t] * g_u[t];
#pragma unroll
    for (int o = 16; o; o >>= 1) pv += __shfl_down_sync(0xffffffffu, pv, o);
    if (lane == 0) s_red[w] = pv;

    // anchor tile -> smem (64 KB, float4 coalesced)
    const float4* a4 = reinterpret_cast<const float4*>(anchor + (size_t)row * AA * DD);
    float4* sA4 = reinterpret_cast<float4*>(sA);
#pragma unroll
    for (int i = 0; i < 16; ++i) sA4[t + i * 256] = a4[t + i * 256];
    __syncthreads();

    float qb;
    {
        float s = s_red[0];
#pragma unroll
        for (int i = 1; i < 8; ++i) s += s_red[i];
        qb = s + g_c;
    }

    // scores: warp w handles rows a = w + 8*r
#pragma unroll
    for (int r = 0; r < 8; ++r) {
        int a = w + r * 8;
        const float* ar = sA + a * DD;
        float s = 0.f;
#pragma unroll
        for (int j = 0; j < 8; ++j) s = fmaf(sQk[lane + 32 * j], ar[lane + 32 * j], s);
#pragma unroll
        for (int o = 16; o; o >>= 1) s += __shfl_down_sync(0xffffffffu, s, o);
        if (lane == 0) s_adj[a] = s + qb + sims[row * AA + a];
    }
    __syncthreads();

    // conditional softmax (warp 0 owns all 64 logits)
    if (w == 0) {
        float v0 = s_adj[lane], v1 = s_adj[lane + 32];
        float sum = v0 + v1;
#pragma unroll
        for (int o = 16; o; o >>= 1) sum += __shfl_xor_sync(0xffffffffu, sum, o);
        if (sum != 0.0f) {
            float m = fmaxf(v0, v1);
#pragma unroll
            for (int o = 16; o; o >>= 1) m = fmaxf(m, __shfl_xor_sync(0xffffffffu, m, o));
            float e0 = expf(v0 - m), e1 = expf(v1 - m);
            float es = e0 + e1;
#pragma unroll
            for (int o = 16; o; o >>= 1) es += __shfl_xor_sync(0xffffffffu, es, o);
            float p0 = e0 / es, p1 = e1 / es;
            s_p[lane] = p0;
            s_p[lane + 32] = p1;
            float ps = p0 + p1;
#pragma unroll
            for (int o = 16; o; o >>= 1) ps += __shfl_xor_sync(0xffffffffu, ps, o);
            if (lane == 0) g_S[row] = ps;
        } else {
            s_p[lane] = v0;
            s_p[lane + 32] = v1;
            if (lane == 0) g_S[row] = sum;  // == 0
        }
    }
    __syncthreads();

    // weighted sum over the smem tile: wsum[e] = sum_a p[a]*anchor[a][e]
    float acc0 = 0.f, acc1 = 0.f;
#pragma unroll
    for (int a = 0; a < AA; a += 2) {
        acc0 = fmaf(s_p[a + 0], sA[(a + 0) * DD + t], acc0);
        acc1 = fmaf(s_p[a + 1], sA[(a + 1) * DD + t], acc1);
    }
    g_wsum[row * DD + t] = acc0 + acc1;
}

// ---------------- kernel D: out = g_wsum @ Wv^T + bv * S --------------------
__global__ __launch_bounds__(256) void gemm_out(const float* __restrict__ Wv,
                                                const float* __restrict__ bv,
                                                float* __restrict__ out) {
    __shared__ float As[16][68];
    __shared__ float Bs[16][68];
    int tx = threadIdx.x % 16, ty = threadIdx.x / 16;
    int m0 = blockIdx.x * 64, n0 = blockIdx.y * 64;
    int lm = threadIdx.x / 4, lkg = threadIdx.x % 4;
    float acc[4][4] = {};
    for (int k0 = 0; k0 < DD; k0 += 16) {
        float4 a = *reinterpret_cast<const float4*>(g_wsum + (m0 + lm) * DD + k0 + lkg * 4);
        As[lkg * 4 + 0][lm] = a.x;
        As[lkg * 4 + 1][lm] = a.y;
        As[lkg * 4 + 2][lm] = a.z;
        As[lkg * 4 + 3][lm] = a.w;
        // Bs[k][n] = Wv[(n0+n)*D + k0+k]   (transposed load)
        float4 b = *reinterpret_cast<const float4*>(Wv + (n0 + lm) * DD + k0 + lkg * 4);
        Bs[lkg * 4 + 0][lm] = b.x;
        Bs[lkg * 4 + 1][lm] = b.y;
        Bs[lkg * 4 + 2][lm] = b.z;
        Bs[lkg * 4 + 3][lm] = b.w;
        __syncthreads();
        mma_tile(As, Bs, ty, tx, acc);
        __syncthreads();
    }
#pragma unroll
    for (int i = 0; i < 4; ++i) {
        int m = m0 + ty * 4 + i;
        float Sv = g_S[m];
#pragma unroll
        for (int j = 0; j < 4; ++j)
            out[m * DD + n0 + tx * 4 + j] = acc[i][j] + bv[n0 + tx * 4 + j] * Sv;
    }
}

// ---------------- launch ----------------------------------------------------
extern "C" void kernel_launch(void* const* d_in, const int* in_sizes, int n_in,
                              void* d_out, int out_size) {
    const float* cc     = (const float*)d_in[0];
    const float* anchor = (const float*)d_in[1];
    const float* sims   = (const float*)d_in[2];
    const float* Wq     = (const float*)d_in[3];
    const float* bq     = (const float*)d_in[4];
    const float* Wk     = (const float*)d_in[5];
    const float* bk     = (const float*)d_in[6];
    const float* Wv     = (const float*)d_in[7];
    const float* bv     = (const float*)d_in[8];
    float* out = (float*)d_out;

    const int smem_attn = (AA * DD + DD) * (int)sizeof(float);  // 66560 B
    cudaFuncSetAttribute(attn_fused, cudaFuncAttributeMaxDynamicSharedMemorySize,
                         smem_attn);

    prep_w2<<<dim3(4, 4), 256>>>(Wq, Wk);
    prep_vec<<<2, 256>>>(Wq, bq, Wk, bk);
    gemm_qk<<<dim3(64, 4), 256>>>(cc);
    attn_fused<<<NROWS, 256, smem_attn>>>(anchor, sims, cc);
    gemm_out<<<dim3(64, 4), 256>>>(Wv, bv, out);
}

// round 5
// speedup vs baseline: 1.0539x; 1.0427x over previous
#include <cuda_runtime.h>
#include <math.h>
#include <stdint.h>

#define DD 256
#define AA 64
#define NROWS 4096   // B*N
#define NCTA 148     // persistent CTAs for attn (<= SM count)

// ---------------- scratch (device globals; no allocation allowed) ----------
__device__ float g_W2[DD * DD];      // scale * Wq^T @ Wk
__device__ float g_b2[DD];           // scale * bq @ Wk
__device__ float g_u[DD];            // scale * Wq^T @ bk
__device__ float g_c;                // scale * bq . bk
__device__ float g_Qk[NROWS * DD];   // cc @ g_W2 + g_b2
__device__ float g_wsum[NROWS * DD]; // sum_a p[a] * anchor[a,:]
__device__ float g_S[NROWS];         // sum_a p[a]

// ---------------- f32x2 helpers ---------------------------------------------
__device__ __forceinline__ unsigned long long pack2(float x, float y) {
    unsigned long long r;
    asm("mov.b64 %0, {%1, %2};" : "=l"(r) : "f"(x), "f"(y));
    return r;
}
__device__ __forceinline__ void unpack2(unsigned long long v, float& x, float& y) {
    asm("mov.b64 {%0, %1}, %2;" : "=f"(x), "=f"(y) : "l"(v));
}
__device__ __forceinline__ void fma2(unsigned long long& d, unsigned long long a,
                                     unsigned long long b) {
    asm("fma.rn.f32x2 %0, %1, %2, %0;" : "+l"(d) : "l"(a), "l"(b));
}

// ---------------- kernel A: g_W2 = scale * Wq^T @ Wk ------------------------
__device__ __forceinline__ void mma_tile(const float (*As)[68], const float (*Bs)[68],
                                         int ty, int tx, float acc[4][4]) {
#pragma unroll
    for (int kk = 0; kk < 16; ++kk) {
        float4 av = *reinterpret_cast<const float4*>(&As[kk][ty * 4]);
        float4 bv = *reinterpret_cast<const float4*>(&Bs[kk][tx * 4]);
        float ar[4] = {av.x, av.y, av.z, av.w};
        float br[4] = {bv.x, bv.y, bv.z, bv.w};
#pragma unroll
        for (int i = 0; i < 4; ++i)
#pragma unroll
            for (int j = 0; j < 4; ++j)
                acc[i][j] = fmaf(ar[i], br[j], acc[i][j]);
    }
}

__global__ __launch_bounds__(256) void prep_w2(const float* __restrict__ Wq,
                                               const float* __restrict__ Wk) {
    __shared__ float As[16][68];
    __shared__ float Bs[16][68];
    const float scale = 0.0625f;  // 1/sqrt(256)
    int tx = threadIdx.x % 16, ty = threadIdx.x / 16;
    int d0 = blockIdx.x * 64, e0 = blockIdx.y * 64;
    float acc[4][4] = {};
    for (int k0 = 0; k0 < DD; k0 += 16) {
        float4 a = *reinterpret_cast<const float4*>(Wq + (k0 + ty) * DD + d0 + tx * 4);
        float4 b = *reinterpret_cast<const float4*>(Wk + (k0 + ty) * DD + e0 + tx * 4);
        *reinterpret_cast<float4*>(&As[ty][tx * 4]) = a;
        *reinterpret_cast<float4*>(&Bs[ty][tx * 4]) = b;
        __syncthreads();
        mma_tile(As, Bs, ty, tx, acc);
        __syncthreads();
    }
#pragma unroll
    for (int i = 0; i < 4; ++i)
#pragma unroll
        for (int j = 0; j < 4; ++j)
            g_W2[(d0 + ty * 4 + i) * DD + e0 + tx * 4 + j] = scale * acc[i][j];
}

// ---------------- kernel A2: bias vectors ----------------------------------
__global__ __launch_bounds__(256) void prep_vec(const float* __restrict__ Wq,
                                                const float* __restrict__ bq,
                                                const float* __restrict__ Wk,
                                                const float* __restrict__ bk) {
    const float scale = 0.0625f;
    int t = threadIdx.x;
    if (blockIdx.x == 0) {
        float s = 0.f;
        for (int k = 0; k < DD; ++k) s = fmaf(Wq[k * DD + t], bk[k], s);
        g_u[t] = scale * s;
        if (t == 0) {
            float c = 0.f;
            for (int k = 0; k < DD; ++k) c = fmaf(bq[k], bk[k], c);
            g_c = scale * c;
        }
    } else {
        float s = 0.f;
        for (int k = 0; k < DD; ++k) s = fmaf(bq[k], Wk[k * DD + t], s);
        g_b2[t] = scale * s;
    }
}

// ---------------- big GEMM: C[4096,256] = A @ B (+bias) with FFMA2 ----------
// BMODE 0: A = Ap (cc), B = g_W2 [K,N] row-major, C = g_Qk, bias = g_b2[n]
// BMODE 1: A = g_wsum, B = Bp (Wv [N,K] -> transposed), C = Cp (out),
//          bias = biasp[n] * g_S[m]
template <int BMODE>
__global__ __launch_bounds__(256) void gemm128(const float* __restrict__ Ap,
                                               const float* __restrict__ Bp,
                                               const float* __restrict__ biasp,
                                               float* __restrict__ Cp) {
    __shared__ float As[2][16][132];  // [k][m], 132 stride: 16B-aligned rows
    __shared__ float Bs[2][16][68];   // [k][n]

    const float* A = (BMODE == 0) ? Ap : g_wsum;
    const float* B = (BMODE == 0) ? g_W2 : Bp;
    const float* bias = (BMODE == 0) ? g_b2 : biasp;
    float* C = (BMODE == 0) ? g_Qk : Cp;

    const int t = threadIdx.x;
    const int tx = t & 15, ty = t >> 4;
    const int m0 = blockIdx.x * 128, n0 = blockIdx.y * 64;
    const int lmA = t >> 1, kA = (t & 1) * 8;   // A staging
    const int kB = t >> 4, nB = (t & 15) * 4;   // B staging (BMODE 0)
    const int nW = t >> 2, kW = (t & 3) * 4;    // B staging (BMODE 1)

    float4 a0, a1, b0;
    a0 = *reinterpret_cast<const float4*>(A + (m0 + lmA) * DD + kA);
    a1 = *reinterpret_cast<const float4*>(A + (m0 + lmA) * DD + kA + 4);
    if (BMODE == 0)
        b0 = *reinterpret_cast<const float4*>(B + kB * DD + n0 + nB);
    else
        b0 = *reinterpret_cast<const float4*>(B + (n0 + nW) * DD + kW);
    {
        float av[8] = {a0.x, a0.y, a0.z, a0.w, a1.x, a1.y, a1.z, a1.w};
#pragma unroll
        for (int c = 0; c < 8; ++c) As[0][kA + c][lmA] = av[c];
        if (BMODE == 0) {
            *reinterpret_cast<float4*>(&Bs[0][kB][nB]) = b0;
        } else {
            float bvv[4] = {b0.x, b0.y, b0.z, b0.w};
#pragma unroll
            for (int c = 0; c < 4; ++c) Bs[0][kW + c][nW] = bvv[c];
        }
    }
    __syncthreads();

    unsigned long long acc[4][4];
#pragma unroll
    for (int i = 0; i < 4; ++i)
#pragma unroll
        for (int j = 0; j < 4; ++j) acc[i][j] = pack2(0.f, 0.f);

    for (int c = 0; c < 16; ++c) {
        const int buf = c & 1;
        if (c + 1 < 16) {
            const int k0 = (c + 1) * 16;
            a0 = *reinterpret_cast<const float4*>(A + (m0 + lmA) * DD + k0 + kA);
            a1 = *reinterpret_cast<const float4*>(A + (m0 + lmA) * DD + k0 + kA + 4);
            if (BMODE == 0)
                b0 = *reinterpret_cast<const float4*>(B + (k0 + kB) * DD + n0 + nB);
            else
                b0 = *reinterpret_cast<const float4*>(B + (n0 + nW) * DD + k0 + kW);
        }
#pragma unroll
        for (int kk = 0; kk < 16; ++kk) {
            const ulonglong2* ap =
                reinterpret_cast<const ulonglong2*>(&As[buf][kk][ty * 8]);
            ulonglong2 A01 = ap[0], A23 = ap[1];
            float4 bf = *reinterpret_cast<const float4*>(&Bs[buf][kk][tx * 4]);
            unsigned long long bd0 = pack2(bf.x, bf.x), bd1 = pack2(bf.y, bf.y);
            unsigned long long bd2 = pack2(bf.z, bf.z), bd3 = pack2(bf.w, bf.w);
            unsigned long long a2[4] = {A01.x, A01.y, A23.x, A23.y};
#pragma unroll
            for (int i = 0; i < 4; ++i) {
                fma2(acc[i][0], a2[i], bd0);
                fma2(acc[i][1], a2[i], bd1);
                fma2(acc[i][2], a2[i], bd2);
                fma2(acc[i][3], a2[i], bd3);
            }
        }
        if (c + 1 < 16) {
            float av[8] = {a0.x, a0.y, a0.z, a0.w, a1.x, a1.y, a1.z, a1.w};
#pragma unroll
            for (int c2 = 0; c2 < 8; ++c2) As[buf ^ 1][kA + c2][lmA] = av[c2];
            if (BMODE == 0) {
                *reinterpret_cast<float4*>(&Bs[buf ^ 1][kB][nB]) = b0;
            } else {
                float bvv[4] = {b0.x, b0.y, b0.z, b0.w};
#pragma unroll
                for (int c2 = 0; c2 < 4; ++c2) Bs[buf ^ 1][kW + c2][nW] = bvv[c2];
            }
        }
        __syncthreads();
    }

    float4 bb = *reinterpret_cast<const float4*>(bias + n0 + tx * 4);
#pragma unroll
    for (int i = 0; i < 4; ++i) {
        const int m = m0 + ty * 8 + 2 * i;
        float lo[4], hi[4];
#pragma unroll
        for (int j = 0; j < 4; ++j) unpack2(acc[i][j], lo[j], hi[j]);
        float4 o0, o1;
        if (BMODE == 1) {
            float s0 = g_S[m], s1 = g_S[m + 1];
            o0 = make_float4(lo[0] + bb.x * s0, lo[1] + bb.y * s0,
                             lo[2] + bb.z * s0, lo[3] + bb.w * s0);
            o1 = make_float4(hi[0] + bb.x * s1, hi[1] + bb.y * s1,
                             hi[2] + bb.z * s1, hi[3] + bb.w * s1);
        } else {
            o0 = make_float4(lo[0] + bb.x, lo[1] + bb.y, lo[2] + bb.z, lo[3] + bb.w);
            o1 = make_float4(hi[0] + bb.x, hi[1] + bb.y, hi[2] + bb.z, hi[3] + bb.w);
        }
        *reinterpret_cast<float4*>(C + (size_t)m * DD + n0 + tx * 4) = o0;
        *reinterpret_cast<float4*>(C + (size_t)(m + 1) * DD + n0 + tx * 4) = o1;
    }
}

// ---------------- attn v3: persistent + double-buffered bulk-async ----------
__global__ __launch_bounds__(256) void attn_v3(const float* __restrict__ anchor,
                                               const float* __restrict__ sims,
                                               const float* __restrict__ cc) {
    extern __shared__ float sm[];
    // layout: sm[0 .. 2*16384) = two anchor tiles, then sQk[256]
    float* sQk = sm + 2 * AA * DD;
    __shared__ float s_adj[AA], s_p[AA], s_sims[AA], s_red[8];
    __shared__ __align__(8) unsigned long long mbar[2];

    const int t = threadIdx.x, w = t >> 5, lane = t & 31;
    const int cta = blockIdx.x;
    const int iters = (NROWS - cta + NCTA - 1) / NCTA;

    uint32_t mb_base, sA_addr;
    asm("{ .reg .u64 x; cvta.to.shared.u64 x, %1; cvt.u32.u64 %0, x; }"
        : "=r"(mb_base) : "l"(mbar));
    asm("{ .reg .u64 x; cvta.to.shared.u64 x, %1; cvt.u32.u64 %0, x; }"
        : "=r"(sA_addr) : "l"(sm));

    if (t == 0) {
        asm volatile("mbarrier.init.shared::cta.b64 [%0], 1;" :: "r"(mb_base));
        asm volatile("mbarrier.init.shared::cta.b64 [%0], 1;" :: "r"(mb_base + 8));
    }
    __syncthreads();
    if (t == 0) {
        asm volatile("mbarrier.arrive.expect_tx.shared::cta.b64 _, [%0], %1;"
                     :: "r"(mb_base), "r"(65536));
        asm volatile(
            "cp.async.bulk.shared::cta.global.mbarrier::complete_tx::bytes "
            "[%0], [%1], %2, [%3];"
            :: "r"(sA_addr), "l"(anchor + (size_t)cta * AA * DD), "r"(65536),
               "r"(mb_base) : "memory");
        if (iters > 1) {
            asm volatile("mbarrier.arrive.expect_tx.shared::cta.b64 _, [%0], %1;"
                         :: "r"(mb_base + 8), "r"(65536));
            asm volatile(
                "cp.async.bulk.shared::cta.global.mbarrier::complete_tx::bytes "
                "[%0], [%1], %2, [%3];"
                :: "r"(sA_addr + 65536),
                   "l"(anchor + (size_t)(cta + NCTA) * AA * DD), "r"(65536),
                   "r"(mb_base + 8) : "memory");
        }
    }
    int ph0 = 0, ph1 = 0;

    for (int it = 0; it < iters; ++it) {
        const int row = cta + it * NCTA;
        const int b = it & 1;
        const float* sA = sm + b * AA * DD;

        // per-row vectors (overlaps with in-flight DMA)
        sQk[t] = g_Qk[row * DD + t];
        float pv = cc[row * DD + t] * g_u[t];
#pragma unroll
        for (int o = 16; o; o >>= 1) pv += __shfl_down_sync(0xffffffffu, pv, o);
        if (lane == 0) s_red[w] = pv;
        if (t < AA) s_sims[t] = sims[row * AA + t];
        __syncthreads();
        float qb;
        {
            float s = s_red[0];
#pragma unroll
            for (int i = 1; i < 8; ++i) s += s_red[i];
            qb = s + g_c;
        }
        float4 q0 = *reinterpret_cast<const float4*>(&sQk[lane * 4]);
        float4 q1 = *reinterpret_cast<const float4*>(&sQk[(lane + 32) * 4]);

        // wait for this buffer's tile
        {
            uint32_t mb = mb_base + b * 8;
            int p = b ? ph1 : ph0;
            asm volatile(
                "{ .reg .pred P;\n"
                "WL%=: mbarrier.try_wait.parity.acquire.cta.shared::cta.b64 P, [%0], %1;\n"
                "@!P bra WL%=; }"
                :: "r"(mb), "r"(p) : "memory");
        }

        // scores: warp w handles a = w + 8r
#pragma unroll
        for (int r = 0; r < 8; ++r) {
            const int a = w + r * 8;
            const float4* ar = reinterpret_cast<const float4*>(sA + a * DD);
            float4 x0 = ar[lane], x1 = ar[lane + 32];
            float s = q0.x * x0.x + q0.y * x0.y + q0.z * x0.z + q0.w * x0.w +
                      q1.x * x1.x + q1.y * x1.y + q1.z * x1.z + q1.w * x1.w;
#pragma unroll
            for (int o = 16; o; o >>= 1) s += __shfl_down_sync(0xffffffffu, s, o);
            if (lane == 0) s_adj[a] = s + qb + s_sims[a];
        }
        __syncthreads();

        // conditional softmax (warp 0 owns all 64 logits)
        if (w == 0) {
            float v0 = s_adj[lane], v1 = s_adj[lane + 32];
            float sum = v0 + v1;
#pragma unroll
            for (int o = 16; o; o >>= 1) sum += __shfl_xor_sync(0xffffffffu, sum, o);
            if (sum != 0.0f) {
                float m = fmaxf(v0, v1);
#pragma unroll
                for (int o = 16; o; o >>= 1)
                    m = fmaxf(m, __shfl_xor_sync(0xffffffffu, m, o));
                float e0 = expf(v0 - m), e1 = expf(v1 - m);
                float es = e0 + e1;
#pragma unroll
                for (int o = 16; o; o >>= 1) es += __shfl_xor_sync(0xffffffffu, es, o);
                float p0 = e0 / es, p1 = e1 / es;
                s_p[lane] = p0;
                s_p[lane + 32] = p1;
                float ps = p0 + p1;
#pragma unroll
                for (int o = 16; o; o >>= 1) ps += __shfl_xor_sync(0xffffffffu, ps, o);
                if (lane == 0) g_S[row] = ps;
            } else {
                s_p[lane] = v0;
                s_p[lane + 32] = v1;
                if (lane == 0) g_S[row] = sum;  // == 0
            }
        }
        __syncthreads();

        // weighted sum: wsum[t] = sum_a p[a]*anchor[a][t]
        float acc0 = 0.f, acc1 = 0.f;
#pragma unroll
        for (int a = 0; a < AA; a += 2) {
            acc0 = fmaf(s_p[a + 0], sA[(a + 0) * DD + t], acc0);
            acc1 = fmaf(s_p[a + 1], sA[(a + 1) * DD + t], acc1);
        }
        g_wsum[row * DD + t] = acc0 + acc1;
        __syncthreads();  // all reads of sA(b) done

        // refill this buffer for row + 2*NCTA
        if (t == 0 && it + 2 < iters) {
            uint32_t mb = mb_base + b * 8;
            asm volatile("mbarrier.arrive.expect_tx.shared::cta.b64 _, [%0], %1;"
                         :: "r"(mb), "r"(65536));
            asm volatile(
                "cp.async.bulk.shared::cta.global.mbarrier::complete_tx::bytes "
                "[%0], [%1], %2, [%3];"
                :: "r"(sA_addr + b * 65536),
                   "l"(anchor + (size_t)(row + 2 * NCTA) * AA * DD), "r"(65536),
                   "r"(mb) : "memory");
        }
        if (b) ph1 ^= 1; else ph0 ^= 1;
    }
}

// ---------------- launch ----------------------------------------------------
extern "C" void kernel_launch(void* const* d_in, const int* in_sizes, int n_in,
                              void* d_out, int out_size) {
    const float* cc     = (const float*)d_in[0];
    const float* anchor = (const float*)d_in[1];
    const float* sims   = (const float*)d_in[2];
    const float* Wq     = (const float*)d_in[3];
    const float* bq     = (const float*)d_in[4];
    const float* Wk     = (const float*)d_in[5];
    const float* bk     = (const float*)d_in[6];
    const float* Wv     = (const float*)d_in[7];
    const float* bv     = (const float*)d_in[8];
    float* out = (float*)d_out;

    const int smem_attn = (2 * AA * DD + DD) * (int)sizeof(float);  // 132096 B
    cudaFuncSetAttribute(attn_v3, cudaFuncAttributeMaxDynamicSharedMemorySize,
                         smem_attn);

    prep_w2<<<dim3(4, 4), 256>>>(Wq, Wk);
    prep_vec<<<2, 256>>>(Wq, bq, Wk, bk);
    gemm128<0><<<dim3(32, 4), 256>>>(cc, nullptr, nullptr, nullptr);
    attn_v3<<<NCTA, 256, smem_attn>>>(anchor, sims, cc);
    gemm128<1><<<dim3(32, 4), 256>>>(nullptr, Wv, bv, out);
}